// round 4
// baseline (speedup 1.0000x reference)
#include <cuda_runtime.h>
#include <cuda_bf16.h>

#define D 128
#define B_MAX 16384

__device__ int g_starts[B_MAX + 1];

// Streaming boundary detection over sorted index: one coalesced pass.
__global__ void bounds_kernel(const int* __restrict__ index, int n, int B) {
    int i = blockIdx.x * blockDim.x + threadIdx.x;
    if (i >= n) return;
    int b = index[i];
    int a = (i == 0) ? -1 : index[i - 1];
    for (int s = a + 1; s <= b; s++) g_starts[s] = i;
    if (i == n - 1) {
        for (int s = b + 1; s <= B; s++) g_starts[s] = n;
    }
}

__device__ __forceinline__ float fast_tanh(float v) {
    float r;
    asm("tanh.approx.f32 %0, %1;" : "=f"(r) : "f"(v));
    return r;
}

// Reload that the compiler cannot CSE with the earlier load (keeps xv out of
// the live range across the reduction -> lower register pressure).
__device__ __forceinline__ float4 ldg_f4_again(const float* p) {
    float4 v;
    asm volatile("ld.global.v4.f32 {%0,%1,%2,%3}, [%4];"
                 : "=f"(v.x), "=f"(v.y), "=f"(v.z), "=f"(v.w) : "l"(p));
    return v;
}

__global__ __launch_bounds__(256, 6) void seg_attn_kernel(
    const float* __restrict__ x,
    const float* __restrict__ refm,
    const float* __restrict__ W,
    const float* __restrict__ bptr,
    float*       __restrict__ out)
{
    const int s    = blockIdx.x;
    const int tid  = threadIdx.x;
    const int w    = tid >> 5;
    const int lane = tid & 31;

    __shared__ float acc_s[8][D];   // 4 KB
    __shared__ float esum_s[8];

    const int start = g_starts[s];
    const int end   = g_starts[s + 1];

    if (start == end) {                       // empty segment -> zeros
        if (tid < D) out[(size_t)s * D + tid] = 0.0f;
        return;
    }

    // W in registers: lane owns feature columns [4*lane, 4*lane+3]
    const float4 Wa = ((const float4*)W)[lane];        // x half
    const float4 Wb = ((const float4*)W)[32 + lane];   // ref half
    const float  bb = bptr[0];

    const float* xlane = x    + (size_t)lane * 4;
    const float* rlane = refm + (size_t)lane * 4;

    float4 acc  = make_float4(0.f, 0.f, 0.f, 0.f);
    float  esum = 0.f;

    const unsigned FULL = 0xffffffffu;

    // 4 rows per warp per iteration; xv not held across the reduction.
    for (int r0 = start + w * 4; r0 < end; r0 += 32) {
        float p[4];
        #pragma unroll
        for (int k = 0; k < 4; k++) {
            const int r = r0 + k;
            float4 xv = make_float4(0.f, 0.f, 0.f, 0.f);
            float4 rv = make_float4(0.f, 0.f, 0.f, 0.f);
            if (r < end) {
                xv = *(const float4*)(xlane + (size_t)r * D);
                rv = *(const float4*)(rlane + (size_t)r * D);
            }
            p[k] = xv.x * Wa.x + xv.y * Wa.y + xv.z * Wa.z + xv.w * Wa.w
                 + rv.x * Wb.x + rv.y * Wb.y + rv.z * Wb.z + rv.w * Wb.w;
        }

        // Tree-merge 4-row reduction: 9 shuffles total.
        // Level xor-16: fold (p0,p1) and (p2,p3) into warp halves.
        float t0 = __shfl_xor_sync(FULL, p[0], 16);
        float t1 = __shfl_xor_sync(FULL, p[1], 16);
        float q0 = (lane & 16) ? (p[1] + t1) : (p[0] + t0);
        float t2 = __shfl_xor_sync(FULL, p[2], 16);
        float t3 = __shfl_xor_sync(FULL, p[3], 16);
        float q1 = (lane & 16) ? (p[3] + t3) : (p[2] + t2);
        // Level xor-8: fold (q0,q1) into warp quarters.
        float u0 = __shfl_xor_sync(FULL, q0, 8);
        float u1 = __shfl_xor_sync(FULL, q1, 8);
        float v  = (lane & 8) ? (q1 + u1) : (q0 + u0);
        // Finish within 8-lane groups.
        v += __shfl_xor_sync(FULL, v, 4);
        v += __shfl_xor_sync(FULL, v, 2);
        v += __shfl_xor_sync(FULL, v, 1);
        // Row sums now live in: lane 0 -> row0, 16 -> row1, 8 -> row2, 24 -> row3.

        // softmax shift-invariant + tanh bounded: no segment max needed.
        const float ev = __expf(fast_tanh(v + bb));
        float e[4];
        e[0] = __shfl_sync(FULL, ev, 0);
        e[1] = __shfl_sync(FULL, ev, 16);
        e[2] = __shfl_sync(FULL, ev, 8);
        e[3] = __shfl_sync(FULL, ev, 24);

        #pragma unroll
        for (int k = 0; k < 4; k++) {
            const int r = r0 + k;
            if (r < end) {
                const float4 xv = ldg_f4_again(xlane + (size_t)r * D);  // L1 hit
                esum  += e[k];
                acc.x += e[k] * xv.x;
                acc.y += e[k] * xv.y;
                acc.z += e[k] * xv.z;
                acc.w += e[k] * xv.w;
            }
        }
    }

    ((float4*)acc_s[w])[lane] = acc;
    if (lane == 0) esum_s[w] = esum;
    __syncthreads();

    if (tid < D) {
        float t = 0.f, es = 0.f;
        #pragma unroll
        for (int i = 0; i < 8; i++) { t += acc_s[i][tid]; es += esum_s[i]; }
        out[(size_t)s * D + tid] = t / (es + 1e-16f);
    }
}

extern "C" void kernel_launch(void* const* d_in, const int* in_sizes, int n_in,
                              void* d_out, int out_size) {
    // metadata order: x, ref, index, batch_size, W, b
    const float* x     = (const float*)d_in[0];
    const float* refm  = (const float*)d_in[1];
    const int*   index = (const int*)  d_in[2];
    const float* W     = (const float*)d_in[4];
    const float* b     = (const float*)d_in[5];
    float* out = (float*)d_out;

    const int n = in_sizes[0] / D;   // 500000
    const int B = out_size / D;      // 16384

    bounds_kernel<<<(n + 255) / 256, 256>>>(index, n, B);
    seg_attn_kernel<<<B, 256>>>(x, refm, W, b, out);
}